// round 1
// baseline (speedup 1.0000x reference)
#include <cuda_runtime.h>
#include <cstdint>

// Problem constants
#define BB 4
#define SS 2048
#define DD 1024
#define HH 16
#define HD 64
#define MM (BB * SS)   // 8192 rows

// Scratch (device globals — allocation-free rule)
__device__ float g_Q[MM * DD];
__device__ float g_K[MM * DD];
__device__ float g_V[MM * DD];
__device__ float g_Oa[MM * DD];

typedef unsigned long long u64;

// ---------- packed f32x2 helpers (ptxas never auto-emits these) ----------
__device__ __forceinline__ u64 ffma2(u64 a, u64 b, u64 c) {
    u64 d;
    asm("fma.rn.f32x2 %0, %1, %2, %3;" : "=l"(d) : "l"(a), "l"(b), "l"(c));
    return d;
}
__device__ __forceinline__ u64 fadd2(u64 a, u64 b) {
    u64 d;
    asm("add.rn.f32x2 %0, %1, %2;" : "=l"(d) : "l"(a), "l"(b));
    return d;
}
__device__ __forceinline__ u64 fdup2(float a) {
    u64 r;
    asm("mov.b64 %0, {%1, %1};" : "=l"(r) : "f"(a));
    return r;
}
__device__ __forceinline__ float2 unpack2(u64 a) {
    float2 f;
    asm("mov.b64 {%0, %1}, %2;" : "=f"(f.x), "=f"(f.y) : "l"(a));
    return f;
}

// ---------- GEMM: C[M,N] = A[M,K] @ B  (B row-major [K,N], or TRANSB: [N,K]) ----------
// M=8192, N=K=1024 fixed. 128x128 tile, BK=8, 256 threads, 8x8 per thread,
// inner product via packed f32x2 (2 cols per FMA).
template <bool TRANSB>
__device__ __forceinline__ void gemm_body(const float* __restrict__ A,
                                          const float* __restrict__ B,
                                          float* __restrict__ C) {
    __shared__ float As[8][128];
    __shared__ float Bs[8][128];

    const int tid = threadIdx.x;
    const int tx = tid & 15;        // 0..15 -> 8 cols each
    const int ty = tid >> 4;        // 0..15 -> 8 rows each
    const int m0 = blockIdx.y * 128;
    const int n0 = blockIdx.x * 128;

    u64 acc[8][4];
#pragma unroll
    for (int i = 0; i < 8; i++)
#pragma unroll
        for (int j = 0; j < 4; j++) acc[i][j] = 0ull;

    const int ar = tid >> 1;            // 0..127
    const int ac = (tid & 1) * 4;       // 0 or 4

    for (int kt = 0; kt < 1024; kt += 8) {
        // A tile (transpose into As[k][m])
        float4 av = *(const float4*)&A[(size_t)(m0 + ar) * 1024 + kt + ac];
        As[ac + 0][ar] = av.x;
        As[ac + 1][ar] = av.y;
        As[ac + 2][ar] = av.z;
        As[ac + 3][ar] = av.w;
        if (!TRANSB) {
            const int br = tid >> 5;             // 0..7
            const int bc = (tid & 31) * 4;       // 0..124
            *(float4*)&Bs[br][bc] =
                *(const float4*)&B[(size_t)(kt + br) * 1024 + n0 + bc];
        } else {
            const int bn = tid >> 1;             // 0..127
            const int bk = (tid & 1) * 4;        // 0 or 4
            float4 bv = *(const float4*)&B[(size_t)(n0 + bn) * 1024 + kt + bk];
            Bs[bk + 0][bn] = bv.x;
            Bs[bk + 1][bn] = bv.y;
            Bs[bk + 2][bn] = bv.z;
            Bs[bk + 3][bn] = bv.w;
        }
        __syncthreads();
#pragma unroll
        for (int k = 0; k < 8; k++) {
            float4 a0 = *(const float4*)&As[k][ty * 8];
            float4 a1 = *(const float4*)&As[k][ty * 8 + 4];
            const u64* bp = (const u64*)&Bs[k][tx * 8];
            u64 b2[4];
            b2[0] = bp[0]; b2[1] = bp[1]; b2[2] = bp[2]; b2[3] = bp[3];
            float af[8] = {a0.x, a0.y, a0.z, a0.w, a1.x, a1.y, a1.z, a1.w};
#pragma unroll
            for (int i = 0; i < 8; i++) {
                u64 ad = fdup2(af[i]);
#pragma unroll
                for (int j = 0; j < 4; j++) acc[i][j] = ffma2(ad, b2[j], acc[i][j]);
            }
        }
        __syncthreads();
    }

#pragma unroll
    for (int i = 0; i < 8; i++) {
        float2 p0 = unpack2(acc[i][0]);
        float2 p1 = unpack2(acc[i][1]);
        float2 p2 = unpack2(acc[i][2]);
        float2 p3 = unpack2(acc[i][3]);
        float4 c0 = make_float4(p0.x, p0.y, p1.x, p1.y);
        float4 c1 = make_float4(p2.x, p2.y, p3.x, p3.y);
        size_t row = (size_t)(m0 + ty * 8 + i);
        *(float4*)&C[row * 1024 + n0 + tx * 8] = c0;
        *(float4*)&C[row * 1024 + n0 + tx * 8 + 4] = c1;
    }
}

__global__ void __launch_bounds__(256)
gemm_qkv_kernel(const float* __restrict__ X,
                const float* __restrict__ Wq,
                const float* __restrict__ Wk,
                const float* __restrict__ Wv) {
    const float* W = (blockIdx.z == 0) ? Wq : ((blockIdx.z == 1) ? Wk : Wv);
    float* C = (blockIdx.z == 0) ? g_Q : ((blockIdx.z == 1) ? g_K : g_V);
    gemm_body<false>(X, W, C);
}

__global__ void __launch_bounds__(256)
gemm_out_kernel(const float* __restrict__ Wo, float* __restrict__ out) {
    gemm_body<true>(g_Oa, Wo, out);
}

// ---------- Causal flash attention, fp32, 1 thread = 1 query row ----------
// BM = 128 query rows per block (128 threads), BN = 64 key tile.
// q and acc held as packed f32x2 registers; K/V tiles broadcast from SMEM.
#define ATTN_SMEM_FLOATS (64 * 64 * 2 + 128 * 65)
#define ATTN_SMEM_BYTES (ATTN_SMEM_FLOATS * 4)

__global__ void __launch_bounds__(128)
attn_kernel() {
    extern __shared__ float sh[];
    float* k_sh = sh;                  // [64][64]
    float* v_sh = sh + 64 * 64;        // [64][64]
    float* p_sh = sh + 2 * 64 * 64;    // [128][65]  (pad 65 -> conflict-free)

    const int tid = threadIdx.x;
    const int bh = blockIdx.y;
    const int b = bh >> 4;
    const int h = bh & 15;
    const int q0 = blockIdx.x * 128;
    const int qg = q0 + tid;

    const float* Qrow = g_Q + ((size_t)(b * SS + qg)) * DD + h * HD;
    u64 q2[32];
    {
        const u64* qp = (const u64*)Qrow;
#pragma unroll
        for (int i = 0; i < 32; i++) q2[i] = qp[i];
    }
    u64 acc2[32];
#pragma unroll
    for (int i = 0; i < 32; i++) acc2[i] = 0ull;
    float m = -1e30f, l = 0.0f;
    float* prow = p_sh + tid * 65;

    const float* Kbase = g_K + ((size_t)(b * SS)) * DD + h * HD;
    const float* Vbase = g_V + ((size_t)(b * SS)) * DD + h * HD;

    const int k_end = q0 + 128;  // causal: keys < q0+BM
    for (int k0 = 0; k0 < k_end; k0 += 64) {
        // load K tile [64 x 64]  (coalesced, 8 float4 per thread)
#pragma unroll
        for (int i = 0; i < 8; i++) {
            int idx = i * 128 + tid;
            int r = idx >> 4, c = (idx & 15) * 4;
            *(float4*)&k_sh[r * 64 + c] =
                *(const float4*)&Kbase[(size_t)(k0 + r) * DD + c];
        }
        __syncthreads();

        // scores for this thread's row
        float mt = -1e30f;
        for (int j = 0; j < 64; j++) {
            const u64* kr = (const u64*)&k_sh[j * 64];
            u64 s0 = 0ull, s1 = 0ull, s2 = 0ull, s3 = 0ull;
#pragma unroll
            for (int i = 0; i < 8; i++) {
                s0 = ffma2(q2[i * 4 + 0], kr[i * 4 + 0], s0);
                s1 = ffma2(q2[i * 4 + 1], kr[i * 4 + 1], s1);
                s2 = ffma2(q2[i * 4 + 2], kr[i * 4 + 2], s2);
                s3 = ffma2(q2[i * 4 + 3], kr[i * 4 + 3], s3);
            }
            u64 st = fadd2(fadd2(s0, s1), fadd2(s2, s3));
            float2 sp = unpack2(st);
            float s = (sp.x + sp.y) * 0.125f;   // 1/sqrt(64)
            if (k0 + j > qg) s = -1e30f;        // causal mask
            prow[j] = s;
            mt = fmaxf(mt, s);
        }

        // online softmax update
        float mn = fmaxf(m, mt);
        float alpha = __expf(m - mn);
        float l0 = 0.0f, l1 = 0.0f;
#pragma unroll 8
        for (int j = 0; j < 64; j += 2) {
            float e0 = __expf(prow[j] - mn);
            float e1 = __expf(prow[j + 1] - mn);
            prow[j] = e0;
            prow[j + 1] = e1;
            l0 += e0;
            l1 += e1;
        }
        l = l * alpha + l0 + l1;
        m = mn;
        u64 a2 = fdup2(alpha);
        u64 z = 0ull;
#pragma unroll
        for (int i = 0; i < 32; i++) acc2[i] = ffma2(acc2[i], a2, z);

        // load V tile
#pragma unroll
        for (int i = 0; i < 8; i++) {
            int idx = i * 128 + tid;
            int r = idx >> 4, c = (idx & 15) * 4;
            *(float4*)&v_sh[r * 64 + c] =
                *(const float4*)&Vbase[(size_t)(k0 + r) * DD + c];
        }
        __syncthreads();

        // PV accumulate (32 independent packed chains — full ILP)
        for (int j = 0; j < 64; j++) {
            u64 p2 = fdup2(prow[j]);
            const u64* vr = (const u64*)&v_sh[j * 64];
#pragma unroll
            for (int i = 0; i < 32; i++) acc2[i] = ffma2(p2, vr[i], acc2[i]);
        }
        // no trailing sync needed: next-iter post-K-load sync guards v_sh reuse
    }

    float inv = 1.0f / l;
    u64 inv2 = fdup2(inv);
    u64 z = 0ull;
    u64* op = (u64*)(g_Oa + ((size_t)(b * SS + qg)) * DD + h * HD);
#pragma unroll
    for (int i = 0; i < 32; i++) op[i] = ffma2(acc2[i], inv2, z);
}

// ---------- launch ----------
extern "C" void kernel_launch(void* const* d_in, const int* in_sizes, int n_in,
                              void* d_out, int out_size) {
    const float* x  = (const float*)d_in[0];
    const float* Wq = (const float*)d_in[1];
    const float* Wk = (const float*)d_in[2];
    const float* Wv = (const float*)d_in[3];
    const float* Wo = (const float*)d_in[4];
    float* out = (float*)d_out;

    cudaFuncSetAttribute(attn_kernel,
                         cudaFuncAttributeMaxDynamicSharedMemorySize,
                         ATTN_SMEM_BYTES);

    dim3 gq(DD / 128, MM / 128, 3);       // (8, 64, 3)
    gemm_qkv_kernel<<<gq, 256>>>(x, Wq, Wk, Wv);

    dim3 ga(SS / 128, BB * HH);           // (16, 64)
    attn_kernel<<<ga, 128, ATTN_SMEM_BYTES>>>();

    dim3 go(DD / 128, MM / 128, 1);       // (8, 64)
    gemm_out_kernel<<<go, 256>>>(Wo, out);
}

// round 3
// speedup vs baseline: 1.4511x; 1.4511x over previous
#include <cuda_runtime.h>
#include <cuda_bf16.h>
#include <cstdint>

// Problem constants
#define BB 4
#define SS 2048
#define DD 1024
#define HH 16
#define HD 64
#define MM (BB * SS)   // 8192 rows

typedef unsigned long long u64;

// ---------------- scratch (device globals; allocation-free rule) ----------------
__device__ float g_Q[MM * DD];
__device__ float g_K[MM * DD];
__device__ float g_V[MM * DD];
__device__ float g_Oa[MM * DD];

__device__ __nv_bfloat16 g_xhi[MM * DD];
__device__ __nv_bfloat16 g_xlo[MM * DD];
__device__ __nv_bfloat16 g_oahi[MM * DD];
__device__ __nv_bfloat16 g_oalo[MM * DD];

// weights: transposed [n][k] for q/k/v; plain [n][k] (= row-major Wo) for o
__device__ __nv_bfloat16 g_wq_hi[DD * DD];
__device__ __nv_bfloat16 g_wq_lo[DD * DD];
__device__ __nv_bfloat16 g_wk_hi[DD * DD];
__device__ __nv_bfloat16 g_wk_lo[DD * DD];
__device__ __nv_bfloat16 g_wv_hi[DD * DD];
__device__ __nv_bfloat16 g_wv_lo[DD * DD];
__device__ __nv_bfloat16 g_wo_hi[DD * DD];
__device__ __nv_bfloat16 g_wo_lo[DD * DD];

// ---------------- PTX helpers (all plain sm_80/90 features, no 'a' suffix) ------
__device__ __forceinline__ uint32_t smem_u32(const void* p) {
    uint32_t a;
    asm("{ .reg .u64 t; cvta.to.shared.u64 t, %1; cvt.u32.u64 %0, t; }" : "=r"(a) : "l"(p));
    return a;
}
__device__ __forceinline__ void cp16(uint32_t dst, const void* src) {
    asm volatile("cp.async.cg.shared.global [%0], [%1], 16;" :: "r"(dst), "l"(src) : "memory");
}
#define CP_COMMIT() asm volatile("cp.async.commit_group;" ::: "memory")
#define CP_WAIT(n) asm volatile("cp.async.wait_group %0;" :: "n"(n) : "memory")

__device__ __forceinline__ void ldm4(uint32_t* d, uint32_t addr) {
    asm volatile("ldmatrix.sync.aligned.m8n8.x4.shared.b16 {%0,%1,%2,%3}, [%4];"
                 : "=r"(d[0]), "=r"(d[1]), "=r"(d[2]), "=r"(d[3]) : "r"(addr));
}
__device__ __forceinline__ void mma16816(float* c, const uint32_t* a, uint32_t b0, uint32_t b1) {
    asm volatile(
        "mma.sync.aligned.m16n8k16.row.col.f32.bf16.bf16.f32 "
        "{%0,%1,%2,%3}, {%4,%5,%6,%7}, {%8,%9}, {%0,%1,%2,%3};"
        : "+f"(c[0]), "+f"(c[1]), "+f"(c[2]), "+f"(c[3])
        : "r"(a[0]), "r"(a[1]), "r"(a[2]), "r"(a[3]), "r"(b0), "r"(b1));
}

// ---------------- packed f32x2 helpers (attention) ----------------
__device__ __forceinline__ u64 ffma2(u64 a, u64 b, u64 c) {
    u64 d;
    asm("fma.rn.f32x2 %0, %1, %2, %3;" : "=l"(d) : "l"(a), "l"(b), "l"(c));
    return d;
}
__device__ __forceinline__ u64 fadd2(u64 a, u64 b) {
    u64 d;
    asm("add.rn.f32x2 %0, %1, %2;" : "=l"(d) : "l"(a), "l"(b));
    return d;
}
__device__ __forceinline__ u64 fdup2(float a) {
    u64 r;
    asm("mov.b64 %0, {%1, %1};" : "=l"(r) : "f"(a));
    return r;
}
__device__ __forceinline__ float2 unpack2(u64 a) {
    float2 f;
    asm("mov.b64 {%0, %1}, %2;" : "=f"(f.x), "=f"(f.y) : "l"(a));
    return f;
}

// ---------------- split / transpose prep kernels ----------------
__global__ void __launch_bounds__(256)
split_kernel(const float* __restrict__ src, __nv_bfloat16* __restrict__ hi,
             __nv_bfloat16* __restrict__ lo, int n4) {
    int i = blockIdx.x * 256 + threadIdx.x;
    if (i >= n4) return;
    float4 v = ((const float4*)src)[i];
    __nv_bfloat16 h0 = __float2bfloat16(v.x);
    __nv_bfloat16 h1 = __float2bfloat16(v.y);
    __nv_bfloat16 h2 = __float2bfloat16(v.z);
    __nv_bfloat16 h3 = __float2bfloat16(v.w);
    __nv_bfloat16 l0 = __float2bfloat16(v.x - __bfloat162float(h0));
    __nv_bfloat16 l1 = __float2bfloat16(v.y - __bfloat162float(h1));
    __nv_bfloat16 l2 = __float2bfloat16(v.z - __bfloat162float(h2));
    __nv_bfloat16 l3 = __float2bfloat16(v.w - __bfloat162float(h3));
    ushort4 hv, lv;
    hv.x = __bfloat16_as_ushort(h0); hv.y = __bfloat16_as_ushort(h1);
    hv.z = __bfloat16_as_ushort(h2); hv.w = __bfloat16_as_ushort(h3);
    lv.x = __bfloat16_as_ushort(l0); lv.y = __bfloat16_as_ushort(l1);
    lv.z = __bfloat16_as_ushort(l2); lv.w = __bfloat16_as_ushort(l3);
    ((ushort4*)hi)[i] = hv;
    ((ushort4*)lo)[i] = lv;
}

// Wt[n][k] = W[k][n], split into hi/lo bf16 (for q/k/v weights)
__global__ void __launch_bounds__(256)
transpose_split_kernel(const float* __restrict__ Wq, const float* __restrict__ Wk,
                       const float* __restrict__ Wv) {
    const float* W = (blockIdx.z == 0) ? Wq : ((blockIdx.z == 1) ? Wk : Wv);
    __nv_bfloat16* hi = (blockIdx.z == 0) ? g_wq_hi : ((blockIdx.z == 1) ? g_wk_hi : g_wv_hi);
    __nv_bfloat16* lo = (blockIdx.z == 0) ? g_wq_lo : ((blockIdx.z == 1) ? g_wk_lo : g_wv_lo);
    __shared__ float t[32][33];
    int tx = threadIdx.x & 31;
    int ty = threadIdx.x >> 5;   // 0..7
    int k0 = blockIdx.y * 32;
    int n0 = blockIdx.x * 32;
#pragma unroll
    for (int i = 0; i < 4; i++)
        t[ty + i * 8][tx] = W[(size_t)(k0 + ty + i * 8) * DD + n0 + tx];
    __syncthreads();
#pragma unroll
    for (int i = 0; i < 4; i++) {
        int n = n0 + ty + i * 8;
        int k = k0 + tx;
        float v = t[tx][ty + i * 8];
        __nv_bfloat16 h = __float2bfloat16(v);
        hi[(size_t)n * DD + k] = h;
        lo[(size_t)n * DD + k] = __float2bfloat16(v - __bfloat162float(h));
    }
}

// ---------------- HMMA split-bf16 GEMM ----------------
// C[M,N] = A @ B^T, A=[M,K] hi/lo bf16, B=[N,K] hi/lo bf16, fp32 accum.
// 128x128 tile, BK=32, 256 threads (8 warps as 4m x 2n), warp tile 32x64.
// SMEM rows padded to 80B (stride 40 bf16) -> conflict-free ldmatrix.
#define BK 32
#define ROWB 80                       // bytes per smem row (32 bf16 + 8 pad)
#define MAT_BYTES (128 * ROWB)        // 10240
#define OFF_AH 0
#define OFF_AL (1 * MAT_BYTES)
#define OFF_BH (2 * MAT_BYTES)
#define OFF_BL (3 * MAT_BYTES)
#define STAGE_BYTES (4 * MAT_BYTES)   // 40960
#define GSMEM_TOTAL (2 * STAGE_BYTES) // 81920

__device__ __forceinline__ void load_stage(uint32_t sb,
                                           const __nv_bfloat16* __restrict__ ahi,
                                           const __nv_bfloat16* __restrict__ alo,
                                           const __nv_bfloat16* __restrict__ bhi,
                                           const __nv_bfloat16* __restrict__ blo,
                                           int m0, int n0, int kt, int tid) {
#pragma unroll
    for (int i = 0; i < 2; i++) {
        int idx = tid + i * 256;          // 0..511
        int r = idx >> 2;                 // 0..127
        int c = idx & 3;                  // 16B chunk
        uint32_t so = (uint32_t)(r * ROWB + c * 16);
        size_t goA = (size_t)(m0 + r) * DD + kt + c * 8;
        size_t goB = (size_t)(n0 + r) * DD + kt + c * 8;
        cp16(sb + OFF_AH + so, ahi + goA);
        cp16(sb + OFF_AL + so, alo + goA);
        cp16(sb + OFF_BH + so, bhi + goB);
        cp16(sb + OFF_BL + so, blo + goB);
    }
}

__device__ __forceinline__ void gemm_core(const __nv_bfloat16* __restrict__ ahi,
                                          const __nv_bfloat16* __restrict__ alo,
                                          const __nv_bfloat16* __restrict__ bhi,
                                          const __nv_bfloat16* __restrict__ blo,
                                          float* __restrict__ C) {
    extern __shared__ char sm[];
    uint32_t sbase = smem_u32(sm);
    const int tid = threadIdx.x;
    const int wid = tid >> 5;
    const int lane = tid & 31;
    const int wm = wid & 3;               // 4 m-blocks of 32 rows
    const int wn = wid >> 2;              // 2 n-blocks of 64 cols
    const int m0 = blockIdx.y * 128;
    const int n0 = blockIdx.x * 128;

    // ldmatrix per-thread address components
    const int g = lane >> 3;              // tile group 0..3
    const int rr = lane & 7;
    // A: g=0: m-lo@k0, g=1: m-hi@k0, g=2: m-lo@k8, g=3: m-hi@k8
    const uint32_t aoff = (uint32_t)((wm * 32 + (g & 1) * 8 + rr) * ROWB + (g >> 1) * 16);
    // B: g=0: n-lo@k0, g=1: n-lo@k8, g=2: n-hi@k0, g=3: n-hi@k8
    const uint32_t boff = (uint32_t)((wn * 64 + (g >> 1) * 8 + rr) * ROWB + (g & 1) * 16);

    float acc[2][8][4];
#pragma unroll
    for (int mi = 0; mi < 2; mi++)
#pragma unroll
        for (int ni = 0; ni < 8; ni++)
#pragma unroll
            for (int j = 0; j < 4; j++) acc[mi][ni][j] = 0.0f;

    const int NST = DD / BK;              // 32
    load_stage(sbase, ahi, alo, bhi, blo, m0, n0, 0, tid);
    CP_COMMIT();

    for (int s = 0; s < NST; s++) {
        if (s + 1 < NST) {
            load_stage(sbase + ((s + 1) & 1) * STAGE_BYTES,
                       ahi, alo, bhi, blo, m0, n0, (s + 1) * BK, tid);
            CP_COMMIT();
            CP_WAIT(1);
        } else {
            CP_WAIT(0);
        }
        __syncthreads();
        uint32_t sb = sbase + (s & 1) * STAGE_BYTES;

#pragma unroll
        for (int kk = 0; kk < 2; kk++) {  // two k16 steps
            uint32_t ah[2][4], al[2][4], bh[4][4], bl[4][4];
#pragma unroll
            for (int mi = 0; mi < 2; mi++) {
                uint32_t ao = sb + aoff + (uint32_t)(mi * 16 * ROWB + kk * 32);
                ldm4(ah[mi], ao + OFF_AH);
                ldm4(al[mi], ao + OFF_AL);
            }
#pragma unroll
            for (int np = 0; np < 4; np++) {
                uint32_t bo = sb + boff + (uint32_t)(np * 16 * ROWB + kk * 32);
                ldm4(bh[np], bo + OFF_BH);
                ldm4(bl[np], bo + OFF_BL);
            }
#pragma unroll
            for (int mi = 0; mi < 2; mi++)
#pragma unroll
                for (int ni = 0; ni < 8; ni++) {
                    int np = ni >> 1;
                    int h = (ni & 1) * 2;
                    mma16816(acc[mi][ni], ah[mi], bh[np][h], bh[np][h + 1]);
                    mma16816(acc[mi][ni], ah[mi], bl[np][h], bl[np][h + 1]);
                    mma16816(acc[mi][ni], al[mi], bh[np][h], bh[np][h + 1]);
                }
        }
        __syncthreads();
    }

    // epilogue
    const int row_b = m0 + wm * 32 + (lane >> 2);
    const int col_b = n0 + wn * 64 + (lane & 3) * 2;
#pragma unroll
    for (int mi = 0; mi < 2; mi++)
#pragma unroll
        for (int ni = 0; ni < 8; ni++) {
            int row = row_b + mi * 16;
            int col = col_b + ni * 8;
            *(float2*)&C[(size_t)row * DD + col] =
                make_float2(acc[mi][ni][0], acc[mi][ni][1]);
            *(float2*)&C[(size_t)(row + 8) * DD + col] =
                make_float2(acc[mi][ni][2], acc[mi][ni][3]);
        }
}

__global__ void __launch_bounds__(256)
gemm_qkv_kernel() {
    const __nv_bfloat16* bhi = (blockIdx.z == 0) ? g_wq_hi : ((blockIdx.z == 1) ? g_wk_hi : g_wv_hi);
    const __nv_bfloat16* blo = (blockIdx.z == 0) ? g_wq_lo : ((blockIdx.z == 1) ? g_wk_lo : g_wv_lo);
    float* C = (blockIdx.z == 0) ? g_Q : ((blockIdx.z == 1) ? g_K : g_V);
    gemm_core(g_xhi, g_xlo, bhi, blo, C);
}

__global__ void __launch_bounds__(256)
gemm_out_kernel(float* __restrict__ out) {
    gemm_core(g_oahi, g_oalo, g_wo_hi, g_wo_lo, out);
}

// ---------------- Causal flash attention, fp32, 1 thread = 1 query row ----------------
#define ATTN_SMEM_FLOATS (64 * 64 * 2 + 128 * 65)
#define ATTN_SMEM_BYTES (ATTN_SMEM_FLOATS * 4)

__global__ void __launch_bounds__(128)
attn_kernel() {
    extern __shared__ float sh[];
    float* k_sh = sh;                  // [64][64]
    float* v_sh = sh + 64 * 64;        // [64][64]
    float* p_sh = sh + 2 * 64 * 64;    // [128][65]

    const int tid = threadIdx.x;
    const int bh = blockIdx.y;
    const int b = bh >> 4;
    const int h = bh & 15;
    const int q0 = blockIdx.x * 128;
    const int qg = q0 + tid;

    const float* Qrow = g_Q + ((size_t)(b * SS + qg)) * DD + h * HD;
    u64 q2[32];
    {
        const u64* qp = (const u64*)Qrow;
#pragma unroll
        for (int i = 0; i < 32; i++) q2[i] = qp[i];
    }
    u64 acc2[32];
#pragma unroll
    for (int i = 0; i < 32; i++) acc2[i] = 0ull;
    float m = -1e30f, l = 0.0f;
    float* prow = p_sh + tid * 65;

    const float* Kbase = g_K + ((size_t)(b * SS)) * DD + h * HD;
    const float* Vbase = g_V + ((size_t)(b * SS)) * DD + h * HD;

    const int k_end = q0 + 128;
    for (int k0 = 0; k0 < k_end; k0 += 64) {
#pragma unroll
        for (int i = 0; i < 8; i++) {
            int idx = i * 128 + tid;
            int r = idx >> 4, c = (idx & 15) * 4;
            *(float4*)&k_sh[r * 64 + c] =
                *(const float4*)&Kbase[(size_t)(k0 + r) * DD + c];
        }
        __syncthreads();

        float mt = -1e30f;
        for (int j = 0; j < 64; j++) {
            const u64* kr = (const u64*)&k_sh[j * 64];
            u64 s0 = 0ull, s1 = 0ull, s2 = 0ull, s3 = 0ull;
#pragma unroll
            for (int i = 0; i < 8; i++) {
                s0 = ffma2(q2[i * 4 + 0], kr[i * 4 + 0], s0);
                s1 = ffma2(q2[i * 4 + 1], kr[i * 4 + 1], s1);
                s2 = ffma2(q2[i * 4 + 2], kr[i * 4 + 2], s2);
                s3 = ffma2(q2[i * 4 + 3], kr[i * 4 + 3], s3);
            }
            u64 st = fadd2(fadd2(s0, s1), fadd2(s2, s3));
            float2 sp = unpack2(st);
            float s = (sp.x + sp.y) * 0.125f;
            if (k0 + j > qg) s = -1e30f;
            prow[j] = s;
            mt = fmaxf(mt, s);
        }

        float mn = fmaxf(m, mt);
        float alpha = __expf(m - mn);
        float l0 = 0.0f, l1 = 0.0f;
#pragma unroll 8
        for (int j = 0; j < 64; j += 2) {
            float e0 = __expf(prow[j] - mn);
            float e1 = __expf(prow[j + 1] - mn);
            prow[j] = e0;
            prow[j + 1] = e1;
            l0 += e0;
            l1 += e1;
        }
        l = l * alpha + l0 + l1;
        m = mn;
        u64 a2 = fdup2(alpha);
        u64 z = 0ull;
#pragma unroll
        for (int i = 0; i < 32; i++) acc2[i] = ffma2(acc2[i], a2, z);

#pragma unroll
        for (int i = 0; i < 8; i++) {
            int idx = i * 128 + tid;
            int r = idx >> 4, c = (idx & 15) * 4;
            *(float4*)&v_sh[r * 64 + c] =
                *(const float4*)&Vbase[(size_t)(k0 + r) * DD + c];
        }
        __syncthreads();

        for (int j = 0; j < 64; j++) {
            u64 p2 = fdup2(prow[j]);
            const u64* vr = (const u64*)&v_sh[j * 64];
#pragma unroll
            for (int i = 0; i < 32; i++) acc2[i] = ffma2(p2, vr[i], acc2[i]);
        }
    }

    float inv = 1.0f / l;
    u64 inv2 = fdup2(inv);
    u64 z = 0ull;
    u64* op = (u64*)(g_Oa + ((size_t)(b * SS + qg)) * DD + h * HD);
#pragma unroll
    for (int i = 0; i < 32; i++) op[i] = ffma2(acc2[i], inv2, z);
}

// ---------------- launch ----------------
extern "C" void kernel_launch(void* const* d_in, const int* in_sizes, int n_in,
                              void* d_out, int out_size) {
    const float* x  = (const float*)d_in[0];
    const float* Wq = (const float*)d_in[1];
    const float* Wk = (const float*)d_in[2];
    const float* Wv = (const float*)d_in[3];
    const float* Wo = (const float*)d_in[4];
    float* out = (float*)d_out;

    cudaFuncSetAttribute(attn_kernel,
                         cudaFuncAttributeMaxDynamicSharedMemorySize, ATTN_SMEM_BYTES);
    cudaFuncSetAttribute(gemm_qkv_kernel,
                         cudaFuncAttributeMaxDynamicSharedMemorySize, GSMEM_TOTAL);
    cudaFuncSetAttribute(gemm_out_kernel,
                         cudaFuncAttributeMaxDynamicSharedMemorySize, GSMEM_TOTAL);

    __nv_bfloat16 *p_xhi, *p_xlo, *p_oahi, *p_oalo, *p_wohi, *p_wolo;
    float* p_oa;
    cudaGetSymbolAddress((void**)&p_xhi, g_xhi);
    cudaGetSymbolAddress((void**)&p_xlo, g_xlo);
    cudaGetSymbolAddress((void**)&p_oahi, g_oahi);
    cudaGetSymbolAddress((void**)&p_oalo, g_oalo);
    cudaGetSymbolAddress((void**)&p_wohi, g_wo_hi);
    cudaGetSymbolAddress((void**)&p_wolo, g_wo_lo);
    cudaGetSymbolAddress((void**)&p_oa, g_Oa);

    split_kernel<<<(MM * DD / 4 + 255) / 256, 256>>>(x, p_xhi, p_xlo, MM * DD / 4);
    split_kernel<<<(DD * DD / 4 + 255) / 256, 256>>>(Wo, p_wohi, p_wolo, DD * DD / 4);
    transpose_split_kernel<<<dim3(32, 32, 3), 256>>>(Wq, Wk, Wv);

    dim3 gq(DD / 128, MM / 128, 3);       // (8, 64, 3)
    gemm_qkv_kernel<<<gq, 256, GSMEM_TOTAL>>>();

    dim3 ga(SS / 128, BB * HH);           // (16, 64)
    attn_kernel<<<ga, 128, ATTN_SMEM_BYTES>>>();

    split_kernel<<<(MM * DD / 4 + 255) / 256, 256>>>(p_oa, p_oahi, p_oalo, MM * DD / 4);

    dim3 go(DD / 128, MM / 128, 1);       // (8, 64)
    gemm_out_kernel<<<go, 256, GSMEM_TOTAL>>>(out);
}